// round 3
// baseline (speedup 1.0000x reference)
#include <cuda_runtime.h>

#define NS    6
#define NC    64
#define HFD   44
#define WFD   80
#define HW    (HFD*WFD)       // 3520
#define ZD    16
#define YD    100
#define XD    100
#define NVOX  (XD*YD*ZD)      // 160000

// Scratch (no cudaMalloc allowed)
__device__ float g_featT[NS*HW*NC];   // [s][h][w][c], channels contiguous
__device__ float g_M[NS][12];         // rows 0..2 of featpix_T_cams @ inv(cam0_T_camXs)
__device__ float g_Zrow[NS][4];       // row 2 of inv(cam0_T_camXs)

// ---------------------------------------------------------------------------
// Kernel 1: combine camera matrices (6 threads)
// ---------------------------------------------------------------------------
__global__ void prep_mats(const float* __restrict__ pix, const float* __restrict__ c0x) {
    int s = threadIdx.x;
    if (s >= NS) return;
    const float* K = pix + s * 16;
    const float* T = c0x + s * 16;

    // rigid inverse of T: [R^T, -R^T t]
    float inv[4][4];
#pragma unroll
    for (int i = 0; i < 4; i++)
#pragma unroll
        for (int j = 0; j < 4; j++) inv[i][j] = 0.f;
#pragma unroll
    for (int i = 0; i < 3; i++)
#pragma unroll
        for (int j = 0; j < 3; j++) inv[i][j] = T[j*4 + i];   // R^T
#pragma unroll
    for (int i = 0; i < 3; i++) {
        float v = 0.f;
#pragma unroll
        for (int j = 0; j < 3; j++) v += T[j*4 + i] * T[j*4 + 3];
        inv[i][3] = -v;
    }
    inv[3][3] = 1.f;

    // featpix = diag(sx, sy, 1, 1) @ K
    const float sx = (float)WFD / 640.0f;   // 0.125
    const float sy = (float)HFD / 352.0f;   // 0.125
    float FP[4][4];
#pragma unroll
    for (int j = 0; j < 4; j++) {
        FP[0][j] = sx * K[j];
        FP[1][j] = sy * K[4 + j];
        FP[2][j] = K[8 + j];
        FP[3][j] = K[12 + j];
    }

    // M = FP @ inv, rows 0..2
#pragma unroll
    for (int i = 0; i < 3; i++)
#pragma unroll
        for (int j = 0; j < 4; j++) {
            float v = 0.f;
#pragma unroll
            for (int k = 0; k < 4; k++) v += FP[i][k] * inv[k][j];
            g_M[s][i*4 + j] = v;
        }
#pragma unroll
    for (int j = 0; j < 4; j++) g_Zrow[s][j] = inv[2][j];
}

// ---------------------------------------------------------------------------
// Kernel 2: transpose features [S,C,H,W] -> [S,H,W,C] (classic 32x32 tile)
// ---------------------------------------------------------------------------
__global__ void transpose_feat(const float* __restrict__ in) {
    __shared__ float tile[32][33];
    int s     = blockIdx.z;
    int pBase = blockIdx.x * 32;   // pixel index h*WFD+w
    int cBase = blockIdx.y * 32;   // channel
    int tx = threadIdx.x, ty = threadIdx.y;  // (32, 8)

    const float* ip = in + s * NC * HW;
#pragma unroll
    for (int k = 0; k < 4; k++) {
        int c = cBase + ty + k*8;
        int p = pBase + tx;
        tile[ty + k*8][tx] = ip[c * HW + p];   // coalesced in p
    }
    __syncthreads();
    float* op = g_featT + s * HW * NC;
#pragma unroll
    for (int k = 0; k < 4; k++) {
        int p = pBase + ty + k*8;
        int c = cBase + tx;
        op[p * NC + c] = tile[tx][ty + k*8];   // coalesced in c
    }
}

// ---------------------------------------------------------------------------
// Kernel 3: project + bilinear sample + camera reduction
// Block: 256 threads, 32 voxels (output-linear-consecutive: fixed x, 2 y, 16 z)
// ---------------------------------------------------------------------------
struct Entry { int o00, o10, o01, o11; float w00, w10, w01, w11; };

__global__ void __launch_bounds__(256) sample_kernel(float* __restrict__ out) {
    __shared__ Entry ent[32][NS];     // 6 KB
    __shared__ int   vmask[32];
    __shared__ float acc[32 * 65];    // 8.3 KB, padded (stride 65) for bank-free writes

    const int tid    = threadIdx.x;
    const int ovBase = blockIdx.x * 32;

    if (tid < 32) vmask[tid] = 0;
    __syncthreads();

    // ---- Projection phase: 192 threads, one (voxel, cam) each ----
    if (tid < 32 * NS) {
        const int vox = tid / NS;
        const int s   = tid - vox * NS;

        const int ov  = ovBase + vox;
        const int ix  = ov / 1600;
        const int rem = ov - ix * 1600;
        const int iy  = rem >> 4;
        const int iz  = rem & 15;

        const float px = fmaf(0.8f, (float)ix + 0.5f, -40.0f);
        const float py = fmaf(0.8f, (float)iy + 0.5f, -40.0f);
        const float pz = fmaf(0.4f, (float)iz + 0.5f, -1.0f);

        const float* M  = g_M[s];
        const float* Zr = g_Zrow[s];
        const float xp = fmaf(M[0], px, fmaf(M[1], py, fmaf(M[2],  pz, M[3])));
        const float yp = fmaf(M[4], px, fmaf(M[5], py, fmaf(M[6],  pz, M[7])));
        const float zp = fmaf(M[8], px, fmaf(M[9], py, fmaf(M[10], pz, M[11])));
        const float zc = fmaf(Zr[0], px, fmaf(Zr[1], py, fmaf(Zr[2], pz, Zr[3])));

        const float denom = fmaxf(zp, 1e-6f);
        const float xpix = xp / denom;
        const float ypix = yp / denom;

        const bool valid = (xpix > -0.5f) && (xpix < (float)WFD - 0.5f) &&
                           (ypix > -0.5f) && (ypix < (float)HFD - 0.5f) &&
                           (zc > 0.0f);
        if (valid) {
            const float x = xpix - 0.5f;
            const float y = ypix - 0.5f;
            const float fx0 = floorf(x), fy0 = floorf(y);
            const float wx1 = x - fx0,   wy1 = y - fy0;
            const float wx0 = 1.f - wx1, wy0 = 1.f - wy1;
            const int ix0 = (int)fx0, iy0 = (int)fy0;
            const bool vx0 = (ix0 >= 0), vy0 = (iy0 >= 0);
            const int cx0 = max(ix0, 0), cy0 = max(iy0, 0);
            const int cx1 = ix0 + 1,     cy1 = iy0 + 1;   // always in-bounds given valid

            Entry e;
            const int base = s * HFD;
            e.o00 = ((base + cy0) * WFD + cx0) * NC;
            e.o10 = ((base + cy0) * WFD + cx1) * NC;
            e.o01 = ((base + cy1) * WFD + cx0) * NC;
            e.o11 = ((base + cy1) * WFD + cx1) * NC;
            e.w00 = (vx0 && vy0) ? wx0 * wy0 : 0.f;
            e.w10 = vy0 ? wx1 * wy0 : 0.f;
            e.w01 = vx0 ? wx0 * wy1 : 0.f;
            e.w11 = wx1 * wy1;
            ent[vox][s] = e;
            atomicOr(&vmask[vox], 1 << s);
        }
    }
    __syncthreads();

    // ---- Sampling phase: warp = 4 voxels, lane = channels (lane, lane+32) ----
    const int warp = tid >> 5;
    const int lane = tid & 31;
    const float* __restrict__ ft = g_featT;

    for (int i = warp * 4; i < warp * 4 + 4; i++) {
        float sum0 = 0.f, sum1 = 0.f, cnt0 = 0.f, cnt1 = 0.f;
        int m = vmask[i];
        while (m) {
            const int s = __ffs(m) - 1;   // ascending camera order -> deterministic sum
            m &= m - 1;
            const Entry e = ent[i][s];    // broadcast from smem
            const float a0 = ft[e.o00 + lane], a1 = ft[e.o00 + lane + 32];
            const float b0 = ft[e.o10 + lane], b1 = ft[e.o10 + lane + 32];
            const float c0 = ft[e.o01 + lane], c1 = ft[e.o01 + lane + 32];
            const float d0 = ft[e.o11 + lane], d1 = ft[e.o11 + lane + 32];
            const float s0 = fmaf(e.w00, a0, fmaf(e.w10, b0, fmaf(e.w01, c0, e.w11 * d0)));
            const float s1 = fmaf(e.w00, a1, fmaf(e.w10, b1, fmaf(e.w01, c1, e.w11 * d1)));
            sum0 += s0; sum1 += s1;
            cnt0 += (s0 != 0.f) ? 1.f : 0.f;
            cnt1 += (s1 != 0.f) ? 1.f : 0.f;
        }
        acc[i * 65 + lane]      = sum0 / (cnt0 + 1e-6f);
        acc[i * 65 + lane + 32] = sum1 / (cnt1 + 1e-6f);
    }
    __syncthreads();

    // ---- Write phase: coalesced 128B stores per channel ----
#pragma unroll
    for (int p = 0; p < 8; p++) {
        const int idx = p * 256 + tid;
        const int c = idx >> 5;
        const int v = idx & 31;
        out[c * NVOX + ovBase + v] = acc[v * 65 + c];
    }
}

// ---------------------------------------------------------------------------
extern "C" void kernel_launch(void* const* d_in, const int* in_sizes, int n_in,
                              void* d_out, int out_size) {
    // Identify features by size (S*C*HF*WF); the two 4x4-stacks keep dict order.
    int fi = 0;
    for (int i = 0; i < n_in; i++)
        if (in_sizes[i] == NS * NC * HFD * WFD) { fi = i; break; }
    int mi0 = -1, mi1 = -1;
    for (int i = 0; i < n_in; i++) {
        if (i == fi) continue;
        if (mi0 < 0) mi0 = i; else if (mi1 < 0) mi1 = i;
    }
    const float* features = (const float*)d_in[fi];
    const float* pix      = (const float*)d_in[mi0];   // pix_T_cams
    const float* c0x      = (const float*)d_in[mi1];   // cam0_T_camXs

    prep_mats<<<1, 32>>>(pix, c0x);

    dim3 tb(32, 8);
    dim3 tg(HW / 32, NC / 32, NS);
    transpose_feat<<<tg, tb>>>(features);

    sample_kernel<<<NVOX / 32, 256>>>((float*)d_out);
}

// round 4
// speedup vs baseline: 1.0145x; 1.0145x over previous
#include <cuda_runtime.h>
#include <cuda_fp16.h>

#define NS    6
#define NC    64
#define HFD   44
#define WFD   80
#define HW    (HFD*WFD)       // 3520
#define ZD    16
#define YD    100
#define XD    100
#define NVOX  (XD*YD*ZD)      // 160000

// Scratch (no cudaMalloc allowed)
__device__ __half g_featT[NS*HW*NC];  // [s][h][w][c], channels contiguous, fp16
__device__ float  g_M[NS][12];        // rows 0..2 of featpix_T_cams @ inv(cam0_T_camXs)
__device__ float  g_Zrow[NS][4];      // row 2 of inv(cam0_T_camXs)

// ---------------------------------------------------------------------------
// Matrix prep (device helper, run by 6 spare threads of transpose block 0)
// ---------------------------------------------------------------------------
__device__ void prep_one(int s, const float* __restrict__ pix,
                         const float* __restrict__ c0x) {
    const float* K = pix + s * 16;
    const float* T = c0x + s * 16;

    // rigid inverse of T: [R^T, -R^T t]
    float inv[4][4];
#pragma unroll
    for (int i = 0; i < 4; i++)
#pragma unroll
        for (int j = 0; j < 4; j++) inv[i][j] = 0.f;
#pragma unroll
    for (int i = 0; i < 3; i++)
#pragma unroll
        for (int j = 0; j < 3; j++) inv[i][j] = T[j*4 + i];   // R^T
#pragma unroll
    for (int i = 0; i < 3; i++) {
        float v = 0.f;
#pragma unroll
        for (int j = 0; j < 3; j++) v += T[j*4 + i] * T[j*4 + 3];
        inv[i][3] = -v;
    }
    inv[3][3] = 1.f;

    // featpix = diag(sx, sy, 1, 1) @ K
    const float sx = (float)WFD / 640.0f;   // 0.125
    const float sy = (float)HFD / 352.0f;   // 0.125
    float FP[4][4];
#pragma unroll
    for (int j = 0; j < 4; j++) {
        FP[0][j] = sx * K[j];
        FP[1][j] = sy * K[4 + j];
        FP[2][j] = K[8 + j];
        FP[3][j] = K[12 + j];
    }

    // M = FP @ inv, rows 0..2
#pragma unroll
    for (int i = 0; i < 3; i++)
#pragma unroll
        for (int j = 0; j < 4; j++) {
            float v = 0.f;
#pragma unroll
            for (int k = 0; k < 4; k++) v += FP[i][k] * inv[k][j];
            g_M[s][i*4 + j] = v;
        }
#pragma unroll
    for (int j = 0; j < 4; j++) g_Zrow[s][j] = inv[2][j];
}

// ---------------------------------------------------------------------------
// Kernel 1: transpose [S,C,H,W] fp32 -> [S,H,W,C] fp16, + fused matrix prep
// ---------------------------------------------------------------------------
__global__ void transpose_feat(const float* __restrict__ in,
                               const float* __restrict__ pix,
                               const float* __restrict__ c0x) {
    __shared__ float tile[32][33];
    int s     = blockIdx.z;
    int pBase = blockIdx.x * 32;   // pixel index h*WFD+w
    int cBase = blockIdx.y * 32;   // channel
    int tx = threadIdx.x, ty = threadIdx.y;  // (32, 8)

    // Fused matrix prep: 6 threads of the first block (independent of transpose)
    if (blockIdx.x == 0 && blockIdx.y == 0 && blockIdx.z == 0 && ty == 7 && tx < NS)
        prep_one(tx, pix, c0x);

    const float* ip = in + s * NC * HW;
#pragma unroll
    for (int k = 0; k < 4; k++) {
        int c = cBase + ty + k*8;
        int p = pBase + tx;
        tile[ty + k*8][tx] = ip[c * HW + p];   // coalesced in p
    }
    __syncthreads();
    __half* op = g_featT + s * HW * NC;
#pragma unroll
    for (int k = 0; k < 4; k++) {
        int p = pBase + ty + k*8;
        int c = cBase + tx;
        op[p * NC + c] = __float2half_rn(tile[tx][ty + k*8]);   // coalesced in c
    }
}

// ---------------------------------------------------------------------------
// Kernel 2: project + bilinear sample (fp16 gathers) + camera reduction
// Block: 256 threads, 32 voxels (output-linear-consecutive: fixed x, 2 y, 16 z)
// ---------------------------------------------------------------------------
struct Entry { int o00, o10, o01, o11; float w00, w10, w01, w11; };  // offsets in half2 units

__global__ void __launch_bounds__(256) sample_kernel(float* __restrict__ out) {
    __shared__ Entry ent[32][NS];     // 6 KB
    __shared__ int   vmask[32];
    __shared__ float acc[32 * 66];    // padded stride (even, but conflicts minor on f2 store)

    const int tid    = threadIdx.x;
    const int ovBase = blockIdx.x * 32;

    if (tid < 32) vmask[tid] = 0;
    __syncthreads();

    // ---- Projection phase: 192 threads, one (voxel, cam) each ----
    if (tid < 32 * NS) {
        const int vox = tid / NS;
        const int s   = tid - vox * NS;

        const int ov  = ovBase + vox;
        const int ix  = ov / 1600;
        const int rem = ov - ix * 1600;
        const int iy  = rem >> 4;
        const int iz  = rem & 15;

        const float px = fmaf(0.8f, (float)ix + 0.5f, -40.0f);
        const float py = fmaf(0.8f, (float)iy + 0.5f, -40.0f);
        const float pz = fmaf(0.4f, (float)iz + 0.5f, -1.0f);

        const float* M  = g_M[s];
        const float* Zr = g_Zrow[s];
        const float xp = fmaf(M[0], px, fmaf(M[1], py, fmaf(M[2],  pz, M[3])));
        const float yp = fmaf(M[4], px, fmaf(M[5], py, fmaf(M[6],  pz, M[7])));
        const float zp = fmaf(M[8], px, fmaf(M[9], py, fmaf(M[10], pz, M[11])));
        const float zc = fmaf(Zr[0], px, fmaf(Zr[1], py, fmaf(Zr[2], pz, Zr[3])));

        const float denom = fmaxf(zp, 1e-6f);
        const float xpix = xp / denom;
        const float ypix = yp / denom;

        const bool valid = (xpix > -0.5f) && (xpix < (float)WFD - 0.5f) &&
                           (ypix > -0.5f) && (ypix < (float)HFD - 0.5f) &&
                           (zc > 0.0f);
        if (valid) {
            const float x = xpix - 0.5f;
            const float y = ypix - 0.5f;
            const float fx0 = floorf(x), fy0 = floorf(y);
            const float wx1 = x - fx0,   wy1 = y - fy0;
            const float wx0 = 1.f - wx1, wy0 = 1.f - wy1;
            const int ix0 = (int)fx0, iy0 = (int)fy0;
            const bool vx0 = (ix0 >= 0), vy0 = (iy0 >= 0);
            const int cx0 = max(ix0, 0), cy0 = max(iy0, 0);
            const int cx1 = ix0 + 1,     cy1 = iy0 + 1;   // in-bounds given valid

            Entry e;
            const int base = s * HFD;
            // offsets in half2 units: pixel * (NC/2)
            e.o00 = ((base + cy0) * WFD + cx0) * (NC/2);
            e.o10 = ((base + cy0) * WFD + cx1) * (NC/2);
            e.o01 = ((base + cy1) * WFD + cx0) * (NC/2);
            e.o11 = ((base + cy1) * WFD + cx1) * (NC/2);
            e.w00 = (vx0 && vy0) ? wx0 * wy0 : 0.f;
            e.w10 = vy0 ? wx1 * wy0 : 0.f;
            e.w01 = vx0 ? wx0 * wy1 : 0.f;
            e.w11 = wx1 * wy1;
            ent[vox][s] = e;
            atomicOr(&vmask[vox], 1 << s);
        }
    }
    __syncthreads();

    // ---- Sampling phase: warp = 4 voxels, lane = channels (2*lane, 2*lane+1) ----
    const int warp = tid >> 5;
    const int lane = tid & 31;
    const __half2* __restrict__ ft2 = reinterpret_cast<const __half2*>(g_featT);

    for (int i = warp * 4; i < warp * 4 + 4; i++) {
        float sum0 = 0.f, sum1 = 0.f, cnt0 = 0.f, cnt1 = 0.f;
        int m = vmask[i];
        while (m) {
            const int s = __ffs(m) - 1;   // ascending camera order -> deterministic sum
            m &= m - 1;
            const Entry e = ent[i][s];    // broadcast from smem
            const float2 a = __half22float2(ft2[e.o00 + lane]);
            const float2 b = __half22float2(ft2[e.o10 + lane]);
            const float2 c = __half22float2(ft2[e.o01 + lane]);
            const float2 d = __half22float2(ft2[e.o11 + lane]);
            const float s0 = fmaf(e.w00, a.x, fmaf(e.w10, b.x, fmaf(e.w01, c.x, e.w11 * d.x)));
            const float s1 = fmaf(e.w00, a.y, fmaf(e.w10, b.y, fmaf(e.w01, c.y, e.w11 * d.y)));
            sum0 += s0; sum1 += s1;
            cnt0 += (s0 != 0.f) ? 1.f : 0.f;
            cnt1 += (s1 != 0.f) ? 1.f : 0.f;
        }
        acc[i * 66 + 2*lane]     = sum0 / (cnt0 + 1e-6f);
        acc[i * 66 + 2*lane + 1] = sum1 / (cnt1 + 1e-6f);
    }
    __syncthreads();

    // ---- Write phase: coalesced 128B stores per channel ----
#pragma unroll
    for (int p = 0; p < 8; p++) {
        const int idx = p * 256 + tid;
        const int c = idx >> 5;
        const int v = idx & 31;
        out[c * NVOX + ovBase + v] = acc[v * 66 + c];
    }
}

// ---------------------------------------------------------------------------
extern "C" void kernel_launch(void* const* d_in, const int* in_sizes, int n_in,
                              void* d_out, int out_size) {
    // Identify features by size (S*C*HF*WF); the two 4x4-stacks keep dict order.
    int fi = 0;
    for (int i = 0; i < n_in; i++)
        if (in_sizes[i] == NS * NC * HFD * WFD) { fi = i; break; }
    int mi0 = -1, mi1 = -1;
    for (int i = 0; i < n_in; i++) {
        if (i == fi) continue;
        if (mi0 < 0) mi0 = i; else if (mi1 < 0) mi1 = i;
    }
    const float* features = (const float*)d_in[fi];
    const float* pix      = (const float*)d_in[mi0];   // pix_T_cams
    const float* c0x      = (const float*)d_in[mi1];   // cam0_T_camXs

    dim3 tb(32, 8);
    dim3 tg(HW / 32, NC / 32, NS);
    transpose_feat<<<tg, tb>>>(features, pix, c0x);

    sample_kernel<<<NVOX / 32, 256>>>((float*)d_out);
}

// round 5
// speedup vs baseline: 1.0735x; 1.0582x over previous
#include <cuda_runtime.h>
#include <cuda_fp16.h>

#define NS    6
#define NC    64
#define HFD   44
#define WFD   80
#define HW    (HFD*WFD)       // 3520
#define ZD    16
#define YD    100
#define XD    100
#define NVOX  (XD*YD*ZD)      // 160000

// Scratch (no cudaMalloc allowed)
__device__ __half g_featT[NS*HW*NC];  // [s][h][w][c], channels contiguous, fp16
__device__ float  g_M[NS][12];        // rows 0..2 of featpix_T_cams @ inv(cam0_T_camXs)
__device__ float  g_Zrow[NS][4];      // row 2 of inv(cam0_T_camXs)

// ---------------------------------------------------------------------------
// Matrix prep (device helper, run by 6 spare threads of transpose block 0)
// ---------------------------------------------------------------------------
__device__ void prep_one(int s, const float* __restrict__ pix,
                         const float* __restrict__ c0x) {
    const float* K = pix + s * 16;
    const float* T = c0x + s * 16;

    float inv[4][4];
#pragma unroll
    for (int i = 0; i < 4; i++)
#pragma unroll
        for (int j = 0; j < 4; j++) inv[i][j] = 0.f;
#pragma unroll
    for (int i = 0; i < 3; i++)
#pragma unroll
        for (int j = 0; j < 3; j++) inv[i][j] = T[j*4 + i];   // R^T
#pragma unroll
    for (int i = 0; i < 3; i++) {
        float v = 0.f;
#pragma unroll
        for (int j = 0; j < 3; j++) v += T[j*4 + i] * T[j*4 + 3];
        inv[i][3] = -v;
    }
    inv[3][3] = 1.f;

    const float sx = (float)WFD / 640.0f;   // 0.125
    const float sy = (float)HFD / 352.0f;   // 0.125
    float FP[4][4];
#pragma unroll
    for (int j = 0; j < 4; j++) {
        FP[0][j] = sx * K[j];
        FP[1][j] = sy * K[4 + j];
        FP[2][j] = K[8 + j];
        FP[3][j] = K[12 + j];
    }

#pragma unroll
    for (int i = 0; i < 3; i++)
#pragma unroll
        for (int j = 0; j < 4; j++) {
            float v = 0.f;
#pragma unroll
            for (int k = 0; k < 4; k++) v += FP[i][k] * inv[k][j];
            g_M[s][i*4 + j] = v;
        }
#pragma unroll
    for (int j = 0; j < 4; j++) g_Zrow[s][j] = inv[2][j];
}

// ---------------------------------------------------------------------------
// Kernel 1: transpose [S,C,H,W] fp32 -> [S,H,W,C] fp16, + fused matrix prep
// ---------------------------------------------------------------------------
__global__ void transpose_feat(const float* __restrict__ in,
                               const float* __restrict__ pix,
                               const float* __restrict__ c0x) {
    __shared__ float tile[32][33];
    int s     = blockIdx.z;
    int pBase = blockIdx.x * 32;
    int cBase = blockIdx.y * 32;
    int tx = threadIdx.x, ty = threadIdx.y;  // (32, 8)

    if (blockIdx.x == 0 && blockIdx.y == 0 && blockIdx.z == 0 && ty == 7 && tx < NS)
        prep_one(tx, pix, c0x);

    const float* ip = in + s * NC * HW;
#pragma unroll
    for (int k = 0; k < 4; k++) {
        int c = cBase + ty + k*8;
        int p = pBase + tx;
        tile[ty + k*8][tx] = ip[c * HW + p];
    }
    __syncthreads();
    __half* op = g_featT + s * HW * NC;
#pragma unroll
    for (int k = 0; k < 4; k++) {
        int p = pBase + ty + k*8;
        int c = cBase + tx;
        op[p * NC + c] = __float2half_rn(tile[tx][ty + k*8]);
    }
}

// ---------------------------------------------------------------------------
// Kernel 2: project + bilinear sample (half2 math) + camera reduction
// Block: 256 threads, 32 voxels (output-linear-consecutive: fixed x, 2 y, 16 z)
// ---------------------------------------------------------------------------
__global__ void __launch_bounds__(256) sample_kernel(float* __restrict__ out) {
    __shared__ int4  ent_o[32][NS];   // 4 corner offsets in half2 units (3 KB)
    __shared__ uint4 ent_w[32][NS];   // 4 broadcast half2 weights       (3 KB)
    __shared__ int   vmask[32];
    __shared__ float acc[32 * 66];    // 8.25 KB

    const int tid    = threadIdx.x;
    const int ovBase = blockIdx.x * 32;

    if (tid < 32) vmask[tid] = 0;
    __syncthreads();

    // ---- Projection phase: 192 threads, one (voxel, cam) each ----
    if (tid < 32 * NS) {
        const int vox = tid / NS;
        const int s   = tid - vox * NS;

        const int ov  = ovBase + vox;
        const int ix  = ov / 1600;
        const int rem = ov - ix * 1600;
        const int iy  = rem >> 4;
        const int iz  = rem & 15;

        const float px = fmaf(0.8f, (float)ix + 0.5f, -40.0f);
        const float py = fmaf(0.8f, (float)iy + 0.5f, -40.0f);
        const float pz = fmaf(0.4f, (float)iz + 0.5f, -1.0f);

        const float* M  = g_M[s];
        const float* Zr = g_Zrow[s];
        const float xp = fmaf(M[0], px, fmaf(M[1], py, fmaf(M[2],  pz, M[3])));
        const float yp = fmaf(M[4], px, fmaf(M[5], py, fmaf(M[6],  pz, M[7])));
        const float zp = fmaf(M[8], px, fmaf(M[9], py, fmaf(M[10], pz, M[11])));
        const float zc = fmaf(Zr[0], px, fmaf(Zr[1], py, fmaf(Zr[2], pz, Zr[3])));

        const float denom = fmaxf(zp, 1e-6f);
        const float xpix = xp / denom;
        const float ypix = yp / denom;

        const bool valid = (xpix > -0.5f) && (xpix < (float)WFD - 0.5f) &&
                           (ypix > -0.5f) && (ypix < (float)HFD - 0.5f) &&
                           (zc > 0.0f);
        if (valid) {
            const float x = xpix - 0.5f;
            const float y = ypix - 0.5f;
            const float fx0 = floorf(x), fy0 = floorf(y);
            const float wx1 = x - fx0,   wy1 = y - fy0;
            const float wx0 = 1.f - wx1, wy0 = 1.f - wy1;
            const int ix0 = (int)fx0, iy0 = (int)fy0;
            const bool vx0 = (ix0 >= 0), vy0 = (iy0 >= 0);
            const int cx0 = max(ix0, 0), cy0 = max(iy0, 0);
            const int cx1 = ix0 + 1,     cy1 = iy0 + 1;   // in-bounds given valid

            const int base = s * HFD;
            int4 o;
            o.x = ((base + cy0) * WFD + cx0) * (NC/2);
            o.y = ((base + cy0) * WFD + cx1) * (NC/2);
            o.z = ((base + cy1) * WFD + cx0) * (NC/2);
            o.w = ((base + cy1) * WFD + cx1) * (NC/2);
            ent_o[vox][s] = o;

            const float w00 = (vx0 && vy0) ? wx0 * wy0 : 0.f;
            const float w10 = vy0 ? wx1 * wy0 : 0.f;
            const float w01 = vx0 ? wx0 * wy1 : 0.f;
            const float w11 = wx1 * wy1;
            uint4 w;
            __half2 h;
            h = __float2half2_rn(w00); w.x = *reinterpret_cast<unsigned*>(&h);
            h = __float2half2_rn(w10); w.y = *reinterpret_cast<unsigned*>(&h);
            h = __float2half2_rn(w01); w.z = *reinterpret_cast<unsigned*>(&h);
            h = __float2half2_rn(w11); w.w = *reinterpret_cast<unsigned*>(&h);
            ent_w[vox][s] = w;

            atomicOr(&vmask[vox], 1 << s);
        }
    }
    __syncthreads();

    // ---- Sampling phase: warp = 4 voxels, lane = channels (2*lane, 2*lane+1) ----
    const int warp = tid >> 5;
    const int lane = tid & 31;
    const __half2* __restrict__ ft2 = reinterpret_cast<const __half2*>(g_featT);
    const __half2 h2zero = __float2half2_rn(0.f);

    for (int i = warp * 4; i < warp * 4 + 4; i++) {
        float sum0 = 0.f, sum1 = 0.f;
        __half2 cnth = h2zero;
        int m = vmask[i];
        while (m) {
            const int s = __ffs(m) - 1;   // ascending camera order -> deterministic sum
            m &= m - 1;
            const int4  o  = ent_o[i][s];    // LDS.128 broadcast
            const uint4 wp = ent_w[i][s];    // LDS.128 broadcast
            const __half2 w00 = *reinterpret_cast<const __half2*>(&wp.x);
            const __half2 w10 = *reinterpret_cast<const __half2*>(&wp.y);
            const __half2 w01 = *reinterpret_cast<const __half2*>(&wp.z);
            const __half2 w11 = *reinterpret_cast<const __half2*>(&wp.w);

            __half2 r = __hmul2(w00, ft2[o.x + lane]);
            r = __hfma2(w10, ft2[o.y + lane], r);
            r = __hfma2(w01, ft2[o.z + lane], r);
            r = __hfma2(w11, ft2[o.w + lane], r);

            const float2 rf = __half22float2(r);
            sum0 += rf.x; sum1 += rf.y;
            cnth = __hadd2(cnth, __hne2(r, h2zero));   // exact integer counts (<=6)
        }
        const float2 cf = __half22float2(cnth);
        acc[i * 66 + 2*lane]     = sum0 / (cf.x + 1e-6f);
        acc[i * 66 + 2*lane + 1] = sum1 / (cf.y + 1e-6f);
    }
    __syncthreads();

    // ---- Write phase: coalesced 128B stores per channel ----
#pragma unroll
    for (int p = 0; p < 8; p++) {
        const int idx = p * 256 + tid;
        const int c = idx >> 5;
        const int v = idx & 31;
        out[c * NVOX + ovBase + v] = acc[v * 66 + c];
    }
}

// ---------------------------------------------------------------------------
extern "C" void kernel_launch(void* const* d_in, const int* in_sizes, int n_in,
                              void* d_out, int out_size) {
    int fi = 0;
    for (int i = 0; i < n_in; i++)
        if (in_sizes[i] == NS * NC * HFD * WFD) { fi = i; break; }
    int mi0 = -1, mi1 = -1;
    for (int i = 0; i < n_in; i++) {
        if (i == fi) continue;
        if (mi0 < 0) mi0 = i; else if (mi1 < 0) mi1 = i;
    }
    const float* features = (const float*)d_in[fi];
    const float* pix      = (const float*)d_in[mi0];   // pix_T_cams
    const float* c0x      = (const float*)d_in[mi1];   // cam0_T_camXs

    dim3 tb(32, 8);
    dim3 tg(HW / 32, NC / 32, NS);
    transpose_feat<<<tg, tb>>>(features, pix, c0x);

    sample_kernel<<<NVOX / 32, 256>>>((float*)d_out);
}

// round 6
// speedup vs baseline: 1.1840x; 1.1029x over previous
#include <cuda_runtime.h>
#include <cuda_fp16.h>

#define NS    6
#define NC    64
#define HFD   44
#define WFD   80
#define HW    (HFD*WFD)       // 3520
#define ZD    16
#define YD    100
#define XD    100
#define NVOX  (XD*YD*ZD)      // 160000

// Scratch (no cudaMalloc allowed)
__device__ __half g_featT[NS*HW*NC];  // [s][h][w][c], channels contiguous, fp16
__device__ float  g_M[NS][12];        // rows 0..2 of featpix_T_cams @ inv(cam0_T_camXs)
__device__ float  g_Zrow[NS][4];      // row 2 of inv(cam0_T_camXs)

// ---------------------------------------------------------------------------
// Matrix prep (device helper, run by 6 spare threads of transpose block 0)
// ---------------------------------------------------------------------------
__device__ void prep_one(int s, const float* __restrict__ pix,
                         const float* __restrict__ c0x) {
    const float* K = pix + s * 16;
    const float* T = c0x + s * 16;

    float inv[4][4];
#pragma unroll
    for (int i = 0; i < 4; i++)
#pragma unroll
        for (int j = 0; j < 4; j++) inv[i][j] = 0.f;
#pragma unroll
    for (int i = 0; i < 3; i++)
#pragma unroll
        for (int j = 0; j < 3; j++) inv[i][j] = T[j*4 + i];   // R^T
#pragma unroll
    for (int i = 0; i < 3; i++) {
        float v = 0.f;
#pragma unroll
        for (int j = 0; j < 3; j++) v += T[j*4 + i] * T[j*4 + 3];
        inv[i][3] = -v;
    }
    inv[3][3] = 1.f;

    const float sx = (float)WFD / 640.0f;   // 0.125
    const float sy = (float)HFD / 352.0f;   // 0.125
    float FP[4][4];
#pragma unroll
    for (int j = 0; j < 4; j++) {
        FP[0][j] = sx * K[j];
        FP[1][j] = sy * K[4 + j];
        FP[2][j] = K[8 + j];
        FP[3][j] = K[12 + j];
    }

#pragma unroll
    for (int i = 0; i < 3; i++)
#pragma unroll
        for (int j = 0; j < 4; j++) {
            float v = 0.f;
#pragma unroll
            for (int k = 0; k < 4; k++) v += FP[i][k] * inv[k][j];
            g_M[s][i*4 + j] = v;
        }
#pragma unroll
    for (int j = 0; j < 4; j++) g_Zrow[s][j] = inv[2][j];
}

// ---------------------------------------------------------------------------
// Kernel 1: transpose [S,C,H,W] fp32 -> [S,H,W,C] fp16, + fused matrix prep
// ---------------------------------------------------------------------------
__global__ void transpose_feat(const float* __restrict__ in,
                               const float* __restrict__ pix,
                               const float* __restrict__ c0x) {
    __shared__ float tile[32][33];
    int s     = blockIdx.z;
    int pBase = blockIdx.x * 32;
    int cBase = blockIdx.y * 32;
    int tx = threadIdx.x, ty = threadIdx.y;  // (32, 8)

    if (blockIdx.x == 0 && blockIdx.y == 0 && blockIdx.z == 0 && ty == 7 && tx < NS)
        prep_one(tx, pix, c0x);

    const float* ip = in + s * NC * HW;
#pragma unroll
    for (int k = 0; k < 4; k++) {
        int c = cBase + ty + k*8;
        int p = pBase + tx;
        tile[ty + k*8][tx] = ip[c * HW + p];
    }
    __syncthreads();
    __half* op = g_featT + s * HW * NC;
#pragma unroll
    for (int k = 0; k < 4; k++) {
        int p = pBase + ty + k*8;
        int c = cBase + tx;
        op[p * NC + c] = __float2half_rn(tile[tx][ty + k*8]);
    }
}

// ---------------------------------------------------------------------------
// Kernel 2: project + bilinear sample (half2 math) + camera reduction
// Block: 256 threads, 32 voxels (output-linear-consecutive: fixed x, 2 y, 16 z)
// ---------------------------------------------------------------------------
__global__ void __launch_bounds__(256) sample_kernel(float* __restrict__ out) {
    __shared__ int4  ent_o[32][NS];   // 4 corner offsets in half2 units (3 KB)
    __shared__ uint4 ent_w[32][NS];   // 4 broadcast half2 weights       (3 KB)
    __shared__ int   vmask[32];
    __shared__ float acc[32 * 66];    // voxel-major, stride 66

    const int tid    = threadIdx.x;
    const int ovBase = blockIdx.x * 32;

    if (tid < 32) vmask[tid] = 0;
    __syncthreads();

    // ---- Projection phase: 192 threads, one (voxel, cam) each ----
    if (tid < 32 * NS) {
        const int vox = tid / NS;
        const int s   = tid - vox * NS;

        const int ov  = ovBase + vox;
        const int ix  = ov / 1600;
        const int rem = ov - ix * 1600;
        const int iy  = rem >> 4;
        const int iz  = rem & 15;

        const float px = fmaf(0.8f, (float)ix + 0.5f, -40.0f);
        const float py = fmaf(0.8f, (float)iy + 0.5f, -40.0f);
        const float pz = fmaf(0.4f, (float)iz + 0.5f, -1.0f);

        const float* M  = g_M[s];
        const float* Zr = g_Zrow[s];
        const float xp = fmaf(M[0], px, fmaf(M[1], py, fmaf(M[2],  pz, M[3])));
        const float yp = fmaf(M[4], px, fmaf(M[5], py, fmaf(M[6],  pz, M[7])));
        const float zp = fmaf(M[8], px, fmaf(M[9], py, fmaf(M[10], pz, M[11])));
        const float zc = fmaf(Zr[0], px, fmaf(Zr[1], py, fmaf(Zr[2], pz, Zr[3])));

        const float rden = __fdividef(1.0f, fmaxf(zp, 1e-6f));
        const float xpix = xp * rden;
        const float ypix = yp * rden;

        const bool valid = (xpix > -0.5f) && (xpix < (float)WFD - 0.5f) &&
                           (ypix > -0.5f) && (ypix < (float)HFD - 0.5f) &&
                           (zc > 0.0f);
        if (valid) {
            const float x = xpix - 0.5f;
            const float y = ypix - 0.5f;
            const float fx0 = floorf(x), fy0 = floorf(y);
            const float wx1 = x - fx0,   wy1 = y - fy0;
            const float wx0 = 1.f - wx1, wy0 = 1.f - wy1;
            const int ix0 = (int)fx0, iy0 = (int)fy0;
            const bool vx0 = (ix0 >= 0), vy0 = (iy0 >= 0);
            const int cx0 = max(ix0, 0), cy0 = max(iy0, 0);
            const int cx1 = ix0 + 1,     cy1 = iy0 + 1;   // in-bounds given valid

            const int base = s * HFD;
            int4 o;
            o.x = ((base + cy0) * WFD + cx0) * (NC/2);
            o.y = ((base + cy0) * WFD + cx1) * (NC/2);
            o.z = ((base + cy1) * WFD + cx0) * (NC/2);
            o.w = ((base + cy1) * WFD + cx1) * (NC/2);
            ent_o[vox][s] = o;

            const float w00 = (vx0 && vy0) ? wx0 * wy0 : 0.f;
            const float w10 = vy0 ? wx1 * wy0 : 0.f;
            const float w01 = vx0 ? wx0 * wy1 : 0.f;
            const float w11 = wx1 * wy1;
            uint4 w;
            __half2 h;
            h = __float2half2_rn(w00); w.x = *reinterpret_cast<unsigned*>(&h);
            h = __float2half2_rn(w10); w.y = *reinterpret_cast<unsigned*>(&h);
            h = __float2half2_rn(w01); w.z = *reinterpret_cast<unsigned*>(&h);
            h = __float2half2_rn(w11); w.w = *reinterpret_cast<unsigned*>(&h);
            ent_w[vox][s] = w;

            atomicOr(&vmask[vox], 1 << s);
        }
    }
    __syncthreads();

    // ---- Sampling phase: warp = 4 voxels, lane = channels (2*lane, 2*lane+1) ----
    const int warp = tid >> 5;
    const int lane = tid & 31;
    const __half2* __restrict__ ft2 = reinterpret_cast<const __half2*>(g_featT);
    const __half2 h2zero = __float2half2_rn(0.f);

    for (int i = warp * 4; i < warp * 4 + 4; i++) {
        float sum0 = 0.f, sum1 = 0.f;
        __half2 cnth = h2zero;
        int m = vmask[i];
        while (m) {
            const int s = __ffs(m) - 1;   // ascending camera order -> deterministic sum
            m &= m - 1;
            const int4  o  = ent_o[i][s];    // LDS.128 broadcast
            const uint4 wp = ent_w[i][s];    // LDS.128 broadcast
            const __half2 w00 = *reinterpret_cast<const __half2*>(&wp.x);
            const __half2 w10 = *reinterpret_cast<const __half2*>(&wp.y);
            const __half2 w01 = *reinterpret_cast<const __half2*>(&wp.z);
            const __half2 w11 = *reinterpret_cast<const __half2*>(&wp.w);

            __half2 r = __hmul2(w00, ft2[o.x + lane]);
            r = __hfma2(w10, ft2[o.y + lane], r);
            r = __hfma2(w01, ft2[o.z + lane], r);
            r = __hfma2(w11, ft2[o.w + lane], r);

            const float2 rf = __half22float2(r);
            sum0 += rf.x; sum1 += rf.y;
            cnth = __hadd2(cnth, __hne2(r, h2zero));   // exact integer counts (<=6)
        }
        const float2 cf = __half22float2(cnth);
        acc[i * 66 + 2*lane]     = sum0 * __fdividef(1.0f, cf.x + 1e-6f);
        acc[i * 66 + 2*lane + 1] = sum1 * __fdividef(1.0f, cf.y + 1e-6f);
    }
    __syncthreads();

    // ---- Write phase: STG.128, warp writes 128B-contiguous per channel ----
    // task: (c, v4) with v4 in 0..7 (4 voxels each). 512 tasks, 2 per thread.
#pragma unroll
    for (int t = 0; t < 2; t++) {
        const int v4 = tid & 7;
        const int c  = (tid >> 3) + t * 32;
        float4 v;
        v.x = acc[(4*v4 + 0) * 66 + c];
        v.y = acc[(4*v4 + 1) * 66 + c];
        v.z = acc[(4*v4 + 2) * 66 + c];
        v.w = acc[(4*v4 + 3) * 66 + c];
        *reinterpret_cast<float4*>(out + c * NVOX + ovBase + 4*v4) = v;
    }
}

// ---------------------------------------------------------------------------
extern "C" void kernel_launch(void* const* d_in, const int* in_sizes, int n_in,
                              void* d_out, int out_size) {
    int fi = 0;
    for (int i = 0; i < n_in; i++)
        if (in_sizes[i] == NS * NC * HFD * WFD) { fi = i; break; }
    int mi0 = -1, mi1 = -1;
    for (int i = 0; i < n_in; i++) {
        if (i == fi) continue;
        if (mi0 < 0) mi0 = i; else if (mi1 < 0) mi1 = i;
    }
    const float* features = (const float*)d_in[fi];
    const float* pix      = (const float*)d_in[mi0];   // pix_T_cams
    const float* c0x      = (const float*)d_in[mi1];   // cam0_T_camXs

    dim3 tb(32, 8);
    dim3 tg(HW / 32, NC / 32, NS);
    transpose_feat<<<tg, tb>>>(features, pix, c0x);

    sample_kernel<<<NVOX / 32, 256>>>((float*)d_out);
}

// round 7
// speedup vs baseline: 1.2271x; 1.0364x over previous
#include <cuda_runtime.h>
#include <cuda_fp16.h>

#define NS    6
#define NC    64
#define HFD   44
#define WFD   80
#define HW    (HFD*WFD)       // 3520
#define ZD    16
#define YD    100
#define XD    100
#define NVOX  (XD*YD*ZD)      // 160000

// Scratch (no cudaMalloc allowed)
__device__ __half g_featT[NS*HW*NC];  // [s][h][w][c], channels contiguous, fp16
__device__ float  g_M[NS][12];        // rows 0..2 of featpix_T_cams @ inv(cam0_T_camXs)
__device__ float  g_Zrow[NS][4];      // row 2 of inv(cam0_T_camXs)

// ---------------------------------------------------------------------------
// Matrix prep (device helper, run by 6 spare threads of transpose block 0)
// ---------------------------------------------------------------------------
__device__ void prep_one(int s, const float* __restrict__ pix,
                         const float* __restrict__ c0x) {
    const float* K = pix + s * 16;
    const float* T = c0x + s * 16;

    float inv[4][4];
#pragma unroll
    for (int i = 0; i < 4; i++)
#pragma unroll
        for (int j = 0; j < 4; j++) inv[i][j] = 0.f;
#pragma unroll
    for (int i = 0; i < 3; i++)
#pragma unroll
        for (int j = 0; j < 3; j++) inv[i][j] = T[j*4 + i];   // R^T
#pragma unroll
    for (int i = 0; i < 3; i++) {
        float v = 0.f;
#pragma unroll
        for (int j = 0; j < 3; j++) v += T[j*4 + i] * T[j*4 + 3];
        inv[i][3] = -v;
    }
    inv[3][3] = 1.f;

    const float sx = (float)WFD / 640.0f;   // 0.125
    const float sy = (float)HFD / 352.0f;   // 0.125
    float FP[4][4];
#pragma unroll
    for (int j = 0; j < 4; j++) {
        FP[0][j] = sx * K[j];
        FP[1][j] = sy * K[4 + j];
        FP[2][j] = K[8 + j];
        FP[3][j] = K[12 + j];
    }

#pragma unroll
    for (int i = 0; i < 3; i++)
#pragma unroll
        for (int j = 0; j < 4; j++) {
            float v = 0.f;
#pragma unroll
            for (int k = 0; k < 4; k++) v += FP[i][k] * inv[k][j];
            g_M[s][i*4 + j] = v;
        }
#pragma unroll
    for (int j = 0; j < 4; j++) g_Zrow[s][j] = inv[2][j];
}

// ---------------------------------------------------------------------------
// Kernel 1: transpose [S,C,H,W] fp32 -> [S,H,W,C] fp16, + fused matrix prep
// ---------------------------------------------------------------------------
__global__ void transpose_feat(const float* __restrict__ in,
                               const float* __restrict__ pix,
                               const float* __restrict__ c0x) {
    __shared__ float tile[32][33];
    int s     = blockIdx.z;
    int pBase = blockIdx.x * 32;
    int cBase = blockIdx.y * 32;
    int tx = threadIdx.x, ty = threadIdx.y;  // (32, 8)

    if (blockIdx.x == 0 && blockIdx.y == 0 && blockIdx.z == 0 && ty == 7 && tx < NS)
        prep_one(tx, pix, c0x);

    const float* ip = in + s * NC * HW;
#pragma unroll
    for (int k = 0; k < 4; k++) {
        int c = cBase + ty + k*8;
        int p = pBase + tx;
        tile[ty + k*8][tx] = ip[c * HW + p];
    }
    __syncthreads();
    __half* op = g_featT + s * HW * NC;
#pragma unroll
    for (int k = 0; k < 4; k++) {
        int p = pBase + ty + k*8;
        int c = cBase + tx;
        op[p * NC + c] = __float2half_rn(tile[tx][ty + k*8]);
    }
}

// ---------------------------------------------------------------------------
// Kernel 2: project + bilinear sample (half2 math) + camera reduction
// Block: 256 threads, 32 voxels (output-linear-consecutive: fixed x, 2 y, 16 z)
// ---------------------------------------------------------------------------
__device__ __forceinline__ __half2 sample_cam(const __half2* __restrict__ ft2,
                                              const int4 o, const uint4 wp,
                                              int lane) {
    const __half2 w00 = *reinterpret_cast<const __half2*>(&wp.x);
    const __half2 w10 = *reinterpret_cast<const __half2*>(&wp.y);
    const __half2 w01 = *reinterpret_cast<const __half2*>(&wp.z);
    const __half2 w11 = *reinterpret_cast<const __half2*>(&wp.w);
    __half2 r = __hmul2(w00, ft2[o.x + lane]);
    r = __hfma2(w10, ft2[o.y + lane], r);
    r = __hfma2(w01, ft2[o.z + lane], r);
    r = __hfma2(w11, ft2[o.w + lane], r);
    return r;
}

__global__ void __launch_bounds__(256) sample_kernel(float* __restrict__ out) {
    __shared__ int4  ent_o[32][NS];   // 4 corner offsets in half2 units (3 KB)
    __shared__ uint4 ent_w[32][NS];   // 4 broadcast half2 weights       (3 KB)
    __shared__ int   vmask[32];
    __shared__ float acc[32 * 66];    // voxel-major, stride 66

    const int tid    = threadIdx.x;
    const int ovBase = blockIdx.x * 32;

    if (tid < 32) vmask[tid] = 0;
    __syncthreads();

    // ---- Projection phase: 192 threads, one (voxel, cam) each ----
    if (tid < 32 * NS) {
        const int vox = tid / NS;
        const int s   = tid - vox * NS;

        const int ov  = ovBase + vox;
        const int ix  = ov / 1600;
        const int rem = ov - ix * 1600;
        const int iy  = rem >> 4;
        const int iz  = rem & 15;

        const float px = fmaf(0.8f, (float)ix + 0.5f, -40.0f);
        const float py = fmaf(0.8f, (float)iy + 0.5f, -40.0f);
        const float pz = fmaf(0.4f, (float)iz + 0.5f, -1.0f);

        const float* M  = g_M[s];
        const float* Zr = g_Zrow[s];
        const float xp = fmaf(M[0], px, fmaf(M[1], py, fmaf(M[2],  pz, M[3])));
        const float yp = fmaf(M[4], px, fmaf(M[5], py, fmaf(M[6],  pz, M[7])));
        const float zp = fmaf(M[8], px, fmaf(M[9], py, fmaf(M[10], pz, M[11])));
        const float zc = fmaf(Zr[0], px, fmaf(Zr[1], py, fmaf(Zr[2], pz, Zr[3])));

        const float rden = __fdividef(1.0f, fmaxf(zp, 1e-6f));
        const float xpix = xp * rden;
        const float ypix = yp * rden;

        const bool valid = (xpix > -0.5f) && (xpix < (float)WFD - 0.5f) &&
                           (ypix > -0.5f) && (ypix < (float)HFD - 0.5f) &&
                           (zc > 0.0f);
        if (valid) {
            const float x = xpix - 0.5f;
            const float y = ypix - 0.5f;
            const float fx0 = floorf(x), fy0 = floorf(y);
            const float wx1 = x - fx0,   wy1 = y - fy0;
            const float wx0 = 1.f - wx1, wy0 = 1.f - wy1;
            const int ix0 = (int)fx0, iy0 = (int)fy0;
            const bool vx0 = (ix0 >= 0), vy0 = (iy0 >= 0);
            const int cx0 = max(ix0, 0), cy0 = max(iy0, 0);
            const int cx1 = ix0 + 1,     cy1 = iy0 + 1;   // in-bounds given valid

            const int base = s * HFD;
            int4 o;
            o.x = ((base + cy0) * WFD + cx0) * (NC/2);
            o.y = ((base + cy0) * WFD + cx1) * (NC/2);
            o.z = ((base + cy1) * WFD + cx0) * (NC/2);
            o.w = ((base + cy1) * WFD + cx1) * (NC/2);
            ent_o[vox][s] = o;

            const float w00 = (vx0 && vy0) ? wx0 * wy0 : 0.f;
            const float w10 = vy0 ? wx1 * wy0 : 0.f;
            const float w01 = vx0 ? wx0 * wy1 : 0.f;
            const float w11 = wx1 * wy1;
            uint4 w;
            __half2 h;
            h = __float2half2_rn(w00); w.x = *reinterpret_cast<unsigned*>(&h);
            h = __float2half2_rn(w10); w.y = *reinterpret_cast<unsigned*>(&h);
            h = __float2half2_rn(w01); w.z = *reinterpret_cast<unsigned*>(&h);
            h = __float2half2_rn(w11); w.w = *reinterpret_cast<unsigned*>(&h);
            ent_w[vox][s] = w;

            atomicOr(&vmask[vox], 1 << s);
        }
    }
    __syncthreads();

    // ---- Sampling phase: warp = 4 voxels, lane = channels (2*lane, 2*lane+1) ----
    // Branch on popc(vmask) is warp-uniform (all lanes share the voxel).
    const int warp = tid >> 5;
    const int lane = tid & 31;
    const __half2* __restrict__ ft2 = reinterpret_cast<const __half2*>(g_featT);
    const __half2 h2zero = __float2half2_rn(0.f);
    const float inv1eps = 0.99999899999f;   // 1/(1+1e-6)

    for (int i = warp * 4; i < warp * 4 + 4; i++) {
        const int m = vmask[i];
        float2* accp = reinterpret_cast<float2*>(&acc[i * 66 + 2*lane]);

        if (m == 0) {
            // no camera sees this voxel -> exactly 0
            *accp = make_float2(0.f, 0.f);
        } else if ((m & (m - 1)) == 0) {
            // single camera (common case ~90%): cnt per channel is (r!=0),
            // so sum/(cnt+eps) == r * 1/(1+eps) for r!=0 and 0 for r==0.
            const int s = __ffs(m) - 1;
            const __half2 r = sample_cam(ft2, ent_o[i][s], ent_w[i][s], lane);
            const float2 rf = __half22float2(r);
            *accp = make_float2(rf.x * inv1eps, rf.y * inv1eps);
        } else {
            float sum0 = 0.f, sum1 = 0.f;
            __half2 cnth = h2zero;
            int mm = m;
            while (mm) {
                const int s = __ffs(mm) - 1;   // ascending order -> deterministic
                mm &= mm - 1;
                const __half2 r = sample_cam(ft2, ent_o[i][s], ent_w[i][s], lane);
                const float2 rf = __half22float2(r);
                sum0 += rf.x; sum1 += rf.y;
                cnth = __hadd2(cnth, __hne2(r, h2zero));   // exact counts (<=6)
            }
            const float2 cf = __half22float2(cnth);
            *accp = make_float2(sum0 * __fdividef(1.0f, cf.x + 1e-6f),
                                sum1 * __fdividef(1.0f, cf.y + 1e-6f));
        }
    }
    __syncthreads();

    // ---- Write phase: STG.128, warp writes 128B-contiguous per channel ----
#pragma unroll
    for (int t = 0; t < 2; t++) {
        const int v4 = tid & 7;
        const int c  = (tid >> 3) + t * 32;
        float4 v;
        v.x = acc[(4*v4 + 0) * 66 + c];
        v.y = acc[(4*v4 + 1) * 66 + c];
        v.z = acc[(4*v4 + 2) * 66 + c];
        v.w = acc[(4*v4 + 3) * 66 + c];
        *reinterpret_cast<float4*>(out + c * NVOX + ovBase + 4*v4) = v;
    }
}

// ---------------------------------------------------------------------------
extern "C" void kernel_launch(void* const* d_in, const int* in_sizes, int n_in,
                              void* d_out, int out_size) {
    int fi = 0;
    for (int i = 0; i < n_in; i++)
        if (in_sizes[i] == NS * NC * HFD * WFD) { fi = i; break; }
    int mi0 = -1, mi1 = -1;
    for (int i = 0; i < n_in; i++) {
        if (i == fi) continue;
        if (mi0 < 0) mi0 = i; else if (mi1 < 0) mi1 = i;
    }
    const float* features = (const float*)d_in[fi];
    const float* pix      = (const float*)d_in[mi0];   // pix_T_cams
    const float* c0x      = (const float*)d_in[mi1];   // cam0_T_camXs

    dim3 tb(32, 8);
    dim3 tg(HW / 32, NC / 32, NS);
    transpose_feat<<<tg, tb>>>(features, pix, c0x);

    sample_kernel<<<NVOX / 32, 256>>>((float*)d_out);
}

// round 8
// speedup vs baseline: 1.2474x; 1.0166x over previous
#include <cuda_runtime.h>
#include <cuda_fp16.h>

#define NS    6
#define NC    64
#define HFD   44
#define WFD   80
#define HW    (HFD*WFD)       // 3520
#define ZD    16
#define YD    100
#define XD    100
#define NVOX  (XD*YD*ZD)      // 160000

// Scratch (no cudaMalloc allowed)
__device__ __half g_featT[NS*HW*NC];  // [s][h][w][c], channels contiguous, fp16
__device__ float  g_M[NS][12];        // rows 0..2 of featpix_T_cams @ inv(cam0_T_camXs)
__device__ float  g_Zrow[NS][4];      // row 2 of inv(cam0_T_camXs)

// ---------------------------------------------------------------------------
// Matrix prep (device helper, run by spare threads of transpose block 0)
// ---------------------------------------------------------------------------
__device__ void prep_one(int s, const float* __restrict__ pix,
                         const float* __restrict__ c0x) {
    const float* K = pix + s * 16;
    const float* T = c0x + s * 16;

    float inv[4][4];
#pragma unroll
    for (int i = 0; i < 4; i++)
#pragma unroll
        for (int j = 0; j < 4; j++) inv[i][j] = 0.f;
#pragma unroll
    for (int i = 0; i < 3; i++)
#pragma unroll
        for (int j = 0; j < 3; j++) inv[i][j] = T[j*4 + i];   // R^T
#pragma unroll
    for (int i = 0; i < 3; i++) {
        float v = 0.f;
#pragma unroll
        for (int j = 0; j < 3; j++) v += T[j*4 + i] * T[j*4 + 3];
        inv[i][3] = -v;
    }
    inv[3][3] = 1.f;

    const float sx = (float)WFD / 640.0f;   // 0.125
    const float sy = (float)HFD / 352.0f;   // 0.125
    float FP[4][4];
#pragma unroll
    for (int j = 0; j < 4; j++) {
        FP[0][j] = sx * K[j];
        FP[1][j] = sy * K[4 + j];
        FP[2][j] = K[8 + j];
        FP[3][j] = K[12 + j];
    }

#pragma unroll
    for (int i = 0; i < 3; i++)
#pragma unroll
        for (int j = 0; j < 4; j++) {
            float v = 0.f;
#pragma unroll
            for (int k = 0; k < 4; k++) v += FP[i][k] * inv[k][j];
            g_M[s][i*4 + j] = v;
        }
#pragma unroll
    for (int j = 0; j < 4; j++) g_Zrow[s][j] = inv[2][j];
}

// ---------------------------------------------------------------------------
// Kernel 1: transpose [S,C,H,W] fp32 -> [S,H,W,C] fp16 (half2 writes),
//           + fused matrix prep.  Tile: 64 channels x 32 pixels.
// ---------------------------------------------------------------------------
__global__ void transpose_feat(const float* __restrict__ in,
                               const float* __restrict__ pix,
                               const float* __restrict__ c0x) {
    __shared__ float tile[64][33];
    const int s     = blockIdx.z;
    const int pBase = blockIdx.x * 32;
    const int tx = threadIdx.x, ty = threadIdx.y;  // (32, 8)

    if (blockIdx.x == 0 && blockIdx.z == 0 && ty == 7 && tx < NS)
        prep_one(tx, pix, c0x);

    const float* ip = in + s * NC * HW;
#pragma unroll
    for (int k = 0; k < 8; k++) {
        int c = ty + k*8;
        tile[c][tx] = ip[c * HW + pBase + tx];   // coalesced in p
    }
    __syncthreads();
    __half2* op = reinterpret_cast<__half2*>(g_featT + s * HW * NC);
#pragma unroll
    for (int k = 0; k < 4; k++) {
        int p = pBase + ty + k*8;
        int pp = ty + k*8;
        __half2 h = __floats2half2_rn(tile[2*tx][pp], tile[2*tx + 1][pp]);
        op[p * (NC/2) + tx] = h;                 // 128B coalesced per warp
    }
}

// ---------------------------------------------------------------------------
// Kernel 2: project + bilinear sample + camera reduction
// Block: 256 threads, 32 voxels. Sampling: warp = 2 voxels at once
// (lane>>4 selects voxel, lane&15 covers 64 channels via uint2 loads).
// ---------------------------------------------------------------------------
__device__ __forceinline__ void sample_cam2(const __half2* __restrict__ ft2,
                                            const int4 o, const uint4 wp,
                                            int hl2, __half2& r0, __half2& r1) {
    const uint2 a = *reinterpret_cast<const uint2*>(ft2 + o.x + hl2);
    const uint2 b = *reinterpret_cast<const uint2*>(ft2 + o.y + hl2);
    const uint2 c = *reinterpret_cast<const uint2*>(ft2 + o.z + hl2);
    const uint2 d = *reinterpret_cast<const uint2*>(ft2 + o.w + hl2);
    const __half2 w00 = *reinterpret_cast<const __half2*>(&wp.x);
    const __half2 w10 = *reinterpret_cast<const __half2*>(&wp.y);
    const __half2 w01 = *reinterpret_cast<const __half2*>(&wp.z);
    const __half2 w11 = *reinterpret_cast<const __half2*>(&wp.w);
    r0 = __hmul2(w00, *reinterpret_cast<const __half2*>(&a.x));
    r0 = __hfma2(w10, *reinterpret_cast<const __half2*>(&b.x), r0);
    r0 = __hfma2(w01, *reinterpret_cast<const __half2*>(&c.x), r0);
    r0 = __hfma2(w11, *reinterpret_cast<const __half2*>(&d.x), r0);
    r1 = __hmul2(w00, *reinterpret_cast<const __half2*>(&a.y));
    r1 = __hfma2(w10, *reinterpret_cast<const __half2*>(&b.y), r1);
    r1 = __hfma2(w01, *reinterpret_cast<const __half2*>(&c.y), r1);
    r1 = __hfma2(w11, *reinterpret_cast<const __half2*>(&d.y), r1);
}

__global__ void __launch_bounds__(256) sample_kernel(float* __restrict__ out) {
    __shared__ int4  ent_o[32][NS];   // 4 corner offsets in half2 units (3 KB)
    __shared__ uint4 ent_w[32][NS];   // 4 broadcast half2 weights       (3 KB)
    __shared__ int   vmask[32];
    __shared__ float acc[32 * 68];    // voxel-major, stride 68 (16B aligned rows)

    const int tid    = threadIdx.x;
    const int ovBase = blockIdx.x * 32;

    if (tid < 32) vmask[tid] = 0;
    __syncthreads();

    // ---- Projection phase: 192 threads, one (voxel, cam) each ----
    if (tid < 32 * NS) {
        const int vox = tid / NS;
        const int s   = tid - vox * NS;

        const int ov  = ovBase + vox;
        const int ix  = ov / 1600;
        const int rem = ov - ix * 1600;
        const int iy  = rem >> 4;
        const int iz  = rem & 15;

        const float px = fmaf(0.8f, (float)ix + 0.5f, -40.0f);
        const float py = fmaf(0.8f, (float)iy + 0.5f, -40.0f);
        const float pz = fmaf(0.4f, (float)iz + 0.5f, -1.0f);

        const float* M  = g_M[s];
        const float* Zr = g_Zrow[s];
        const float xp = fmaf(M[0], px, fmaf(M[1], py, fmaf(M[2],  pz, M[3])));
        const float yp = fmaf(M[4], px, fmaf(M[5], py, fmaf(M[6],  pz, M[7])));
        const float zp = fmaf(M[8], px, fmaf(M[9], py, fmaf(M[10], pz, M[11])));
        const float zc = fmaf(Zr[0], px, fmaf(Zr[1], py, fmaf(Zr[2], pz, Zr[3])));

        const float rden = __fdividef(1.0f, fmaxf(zp, 1e-6f));
        const float xpix = xp * rden;
        const float ypix = yp * rden;

        const bool valid = (xpix > -0.5f) && (xpix < (float)WFD - 0.5f) &&
                           (ypix > -0.5f) && (ypix < (float)HFD - 0.5f) &&
                           (zc > 0.0f);
        if (valid) {
            const float x = xpix - 0.5f;
            const float y = ypix - 0.5f;
            const float fx0 = floorf(x), fy0 = floorf(y);
            const float wx1 = x - fx0,   wy1 = y - fy0;
            const float wx0 = 1.f - wx1, wy0 = 1.f - wy1;
            const int ix0 = (int)fx0, iy0 = (int)fy0;
            const bool vx0 = (ix0 >= 0), vy0 = (iy0 >= 0);
            const int cx0 = max(ix0, 0), cy0 = max(iy0, 0);
            const int cx1 = ix0 + 1,     cy1 = iy0 + 1;   // in-bounds given valid

            const int base = s * HFD;
            int4 o;
            o.x = ((base + cy0) * WFD + cx0) * (NC/2);
            o.y = ((base + cy0) * WFD + cx1) * (NC/2);
            o.z = ((base + cy1) * WFD + cx0) * (NC/2);
            o.w = ((base + cy1) * WFD + cx1) * (NC/2);
            ent_o[vox][s] = o;

            const float w00 = (vx0 && vy0) ? wx0 * wy0 : 0.f;
            const float w10 = vy0 ? wx1 * wy0 : 0.f;
            const float w01 = vx0 ? wx0 * wy1 : 0.f;
            const float w11 = wx1 * wy1;
            uint4 w;
            __half2 h;
            h = __float2half2_rn(w00); w.x = *reinterpret_cast<unsigned*>(&h);
            h = __float2half2_rn(w10); w.y = *reinterpret_cast<unsigned*>(&h);
            h = __float2half2_rn(w01); w.z = *reinterpret_cast<unsigned*>(&h);
            h = __float2half2_rn(w11); w.w = *reinterpret_cast<unsigned*>(&h);
            ent_w[vox][s] = w;

            atomicOr(&vmask[vox], 1 << s);
        }
    }
    __syncthreads();

    // ---- Sampling phase: warp processes 2 voxels per pass ----
    const int warp = tid >> 5;
    const int lane = tid & 31;
    const int hl   = lane & 15;      // channel group: channels [4*hl, 4*hl+4)
    const int hl2  = hl * 2;         // in half2 units
    const int vsel = lane >> 4;      // 0/1: which voxel of the pair
    const __half2* __restrict__ ft2 = reinterpret_cast<const __half2*>(g_featT);
    const __half2 h2zero = __float2half2_rn(0.f);
    const float inv1eps = 0.99999899999f;   // 1/(1+1e-6)

#pragma unroll
    for (int it = 0; it < 2; it++) {
        const int vA = warp * 4 + it * 2 + vsel;     // per-lane voxel
        const int m  = vmask[vA];                    // LDS, 2 addrs per warp
        float4* accp = reinterpret_cast<float4*>(&acc[vA * 68 + 4*hl]);

        if (__all_sync(0xffffffffu, (m & (m - 1)) == 0)) {
            // both voxels have <= 1 camera (common case)
            float4 r = make_float4(0.f, 0.f, 0.f, 0.f);
            if (m) {
                const int s = __ffs(m) - 1;          // uniform per half-warp
                __half2 r0, r1;
                sample_cam2(ft2, ent_o[vA][s], ent_w[vA][s], hl2, r0, r1);
                const float2 f0 = __half22float2(r0);
                const float2 f1 = __half22float2(r1);
                r = make_float4(f0.x * inv1eps, f0.y * inv1eps,
                                f1.x * inv1eps, f1.y * inv1eps);
            }
            *accp = r;
        } else {
            float4 sum = make_float4(0.f, 0.f, 0.f, 0.f);
            __half2 cnt0 = h2zero, cnt1 = h2zero;
            int mm = m;
            while (__any_sync(0xffffffffu, mm != 0)) {
                if (mm) {
                    const int s = __ffs(mm) - 1;     // ascending -> deterministic
                    mm &= mm - 1;
                    __half2 r0, r1;
                    sample_cam2(ft2, ent_o[vA][s], ent_w[vA][s], hl2, r0, r1);
                    const float2 f0 = __half22float2(r0);
                    const float2 f1 = __half22float2(r1);
                    sum.x += f0.x; sum.y += f0.y; sum.z += f1.x; sum.w += f1.y;
                    cnt0 = __hadd2(cnt0, __hne2(r0, h2zero));
                    cnt1 = __hadd2(cnt1, __hne2(r1, h2zero));
                }
            }
            const float2 c0 = __half22float2(cnt0);
            const float2 c1 = __half22float2(cnt1);
            *accp = make_float4(sum.x * __fdividef(1.0f, c0.x + 1e-6f),
                                sum.y * __fdividef(1.0f, c0.y + 1e-6f),
                                sum.z * __fdividef(1.0f, c1.x + 1e-6f),
                                sum.w * __fdividef(1.0f, c1.y + 1e-6f));
        }
    }
    __syncthreads();

    // ---- Write phase: STG.128, warp writes 128B-contiguous per channel ----
#pragma unroll
    for (int t = 0; t < 2; t++) {
        const int v4 = tid & 7;
        const int c  = (tid >> 3) + t * 32;
        float4 v;
        v.x = acc[(4*v4 + 0) * 68 + c];
        v.y = acc[(4*v4 + 1) * 68 + c];
        v.z = acc[(4*v4 + 2) * 68 + c];
        v.w = acc[(4*v4 + 3) * 68 + c];
        *reinterpret_cast<float4*>(out + c * NVOX + ovBase + 4*v4) = v;
    }
}

// ---------------------------------------------------------------------------
extern "C" void kernel_launch(void* const* d_in, const int* in_sizes, int n_in,
                              void* d_out, int out_size) {
    int fi = 0;
    for (int i = 0; i < n_in; i++)
        if (in_sizes[i] == NS * NC * HFD * WFD) { fi = i; break; }
    int mi0 = -1, mi1 = -1;
    for (int i = 0; i < n_in; i++) {
        if (i == fi) continue;
        if (mi0 < 0) mi0 = i; else if (mi1 < 0) mi1 = i;
    }
    const float* features = (const float*)d_in[fi];
    const float* pix      = (const float*)d_in[mi0];   // pix_T_cams
    const float* c0x      = (const float*)d_in[mi1];   // cam0_T_camXs

    dim3 tb(32, 8);
    dim3 tg(HW / 32, 1, NS);
    transpose_feat<<<tg, tb>>>(features, pix, c0x);

    sample_kernel<<<NVOX / 32, 256>>>((float*)d_out);
}

// round 9
// speedup vs baseline: 1.2852x; 1.0302x over previous
#include <cuda_runtime.h>
#include <cuda_fp16.h>

#define NS    6
#define NC    64
#define HFD   44
#define WFD   80
#define HW    (HFD*WFD)       // 3520
#define ZD    16
#define YD    100
#define XD    100
#define NVOX  (XD*YD*ZD)      // 160000

// Scratch (no cudaMalloc allowed)
__device__ __half g_featT[NS*HW*NC];  // [s][h][w][c], channels contiguous, fp16
__device__ float  g_M[NS][12];        // rows 0..2 of featpix_T_cams @ inv(cam0_T_camXs)
__device__ float  g_Zrow[NS][4];      // row 2 of inv(cam0_T_camXs)

// ---------------------------------------------------------------------------
// Matrix prep (device helper, run by spare threads of transpose block 0)
// ---------------------------------------------------------------------------
__device__ void prep_one(int s, const float* __restrict__ pix,
                         const float* __restrict__ c0x) {
    const float* K = pix + s * 16;
    const float* T = c0x + s * 16;

    float inv[4][4];
#pragma unroll
    for (int i = 0; i < 4; i++)
#pragma unroll
        for (int j = 0; j < 4; j++) inv[i][j] = 0.f;
#pragma unroll
    for (int i = 0; i < 3; i++)
#pragma unroll
        for (int j = 0; j < 3; j++) inv[i][j] = T[j*4 + i];   // R^T
#pragma unroll
    for (int i = 0; i < 3; i++) {
        float v = 0.f;
#pragma unroll
        for (int j = 0; j < 3; j++) v += T[j*4 + i] * T[j*4 + 3];
        inv[i][3] = -v;
    }
    inv[3][3] = 1.f;

    const float sx = (float)WFD / 640.0f;   // 0.125
    const float sy = (float)HFD / 352.0f;   // 0.125
    float FP[4][4];
#pragma unroll
    for (int j = 0; j < 4; j++) {
        FP[0][j] = sx * K[j];
        FP[1][j] = sy * K[4 + j];
        FP[2][j] = K[8 + j];
        FP[3][j] = K[12 + j];
    }

#pragma unroll
    for (int i = 0; i < 3; i++)
#pragma unroll
        for (int j = 0; j < 4; j++) {
            float v = 0.f;
#pragma unroll
            for (int k = 0; k < 4; k++) v += FP[i][k] * inv[k][j];
            g_M[s][i*4 + j] = v;
        }
#pragma unroll
    for (int j = 0; j < 4; j++) g_Zrow[s][j] = inv[2][j];
}

// ---------------------------------------------------------------------------
// Kernel 1: transpose [S,C,H,W] fp32 -> [S,H,W,C] fp16 (half2 writes),
//           + fused matrix prep.  Tile: 64 channels x 32 pixels.
// ---------------------------------------------------------------------------
__global__ void transpose_feat(const float* __restrict__ in,
                               const float* __restrict__ pix,
                               const float* __restrict__ c0x) {
    __shared__ float tile[64][33];
    const int s     = blockIdx.z;
    const int pBase = blockIdx.x * 32;
    const int tx = threadIdx.x, ty = threadIdx.y;  // (32, 8)

    if (blockIdx.x == 0 && blockIdx.z == 0 && ty == 7 && tx < NS)
        prep_one(tx, pix, c0x);

    const float* ip = in + s * NC * HW;
#pragma unroll
    for (int k = 0; k < 8; k++) {
        int c = ty + k*8;
        tile[c][tx] = ip[c * HW + pBase + tx];   // coalesced in p
    }
    __syncthreads();
    __half2* op = reinterpret_cast<__half2*>(g_featT + s * HW * NC);
#pragma unroll
    for (int k = 0; k < 4; k++) {
        int p = pBase + ty + k*8;
        int pp = ty + k*8;
        __half2 h = __floats2half2_rn(tile[2*tx][pp], tile[2*tx + 1][pp]);
        op[p * (NC/2) + tx] = h;                 // 128B coalesced per warp
    }
}

// ---------------------------------------------------------------------------
// Kernel 2: project + bilinear sample + camera reduction
// Block: 256 threads, 32 voxels. Sampling: warp = 4 voxels per pass
// (lane>>3 selects voxel, lane&7 covers 64 channels via uint4/LDG.128 loads).
// ---------------------------------------------------------------------------
__device__ __forceinline__ void sample_cam4(const __half2* __restrict__ ft2,
                                            const int4 o, const uint4 wp,
                                            int e4, __half2 r[4]) {
    const uint4 a = *reinterpret_cast<const uint4*>(ft2 + o.x + e4);
    const uint4 b = *reinterpret_cast<const uint4*>(ft2 + o.y + e4);
    const uint4 c = *reinterpret_cast<const uint4*>(ft2 + o.z + e4);
    const uint4 d = *reinterpret_cast<const uint4*>(ft2 + o.w + e4);
    const __half2 w00 = *reinterpret_cast<const __half2*>(&wp.x);
    const __half2 w10 = *reinterpret_cast<const __half2*>(&wp.y);
    const __half2 w01 = *reinterpret_cast<const __half2*>(&wp.z);
    const __half2 w11 = *reinterpret_cast<const __half2*>(&wp.w);
    const unsigned* ap = &a.x; const unsigned* bp = &b.x;
    const unsigned* cp = &c.x; const unsigned* dp = &d.x;
#pragma unroll
    for (int j = 0; j < 4; j++) {
        __half2 t = __hmul2(w00, *reinterpret_cast<const __half2*>(&ap[j]));
        t = __hfma2(w10, *reinterpret_cast<const __half2*>(&bp[j]), t);
        t = __hfma2(w01, *reinterpret_cast<const __half2*>(&cp[j]), t);
        t = __hfma2(w11, *reinterpret_cast<const __half2*>(&dp[j]), t);
        r[j] = t;
    }
}

__global__ void __launch_bounds__(256) sample_kernel(float* __restrict__ out) {
    __shared__ int4  ent_o[32][NS];   // 4 corner offsets in half2 units (3 KB)
    __shared__ uint4 ent_w[32][NS];   // 4 broadcast half2 weights       (3 KB)
    __shared__ int   vmask[32];
    __shared__ float acc[32 * 68];    // voxel-major, stride 68 (16B aligned rows)

    const int tid    = threadIdx.x;
    const int ovBase = blockIdx.x * 32;

    if (tid < 32) vmask[tid] = 0;
    __syncthreads();

    // ---- Projection phase: 192 threads, one (voxel, cam) each ----
    if (tid < 32 * NS) {
        const int vox = tid / NS;
        const int s   = tid - vox * NS;

        const int ov  = ovBase + vox;
        const int ix  = ov / 1600;
        const int rem = ov - ix * 1600;
        const int iy  = rem >> 4;
        const int iz  = rem & 15;

        const float px = fmaf(0.8f, (float)ix + 0.5f, -40.0f);
        const float py = fmaf(0.8f, (float)iy + 0.5f, -40.0f);
        const float pz = fmaf(0.4f, (float)iz + 0.5f, -1.0f);

        const float* M  = g_M[s];
        const float* Zr = g_Zrow[s];
        const float xp = fmaf(M[0], px, fmaf(M[1], py, fmaf(M[2],  pz, M[3])));
        const float yp = fmaf(M[4], px, fmaf(M[5], py, fmaf(M[6],  pz, M[7])));
        const float zp = fmaf(M[8], px, fmaf(M[9], py, fmaf(M[10], pz, M[11])));
        const float zc = fmaf(Zr[0], px, fmaf(Zr[1], py, fmaf(Zr[2], pz, Zr[3])));

        const float rden = __fdividef(1.0f, fmaxf(zp, 1e-6f));
        const float xpix = xp * rden;
        const float ypix = yp * rden;

        const bool valid = (xpix > -0.5f) && (xpix < (float)WFD - 0.5f) &&
                           (ypix > -0.5f) && (ypix < (float)HFD - 0.5f) &&
                           (zc > 0.0f);
        if (valid) {
            const float x = xpix - 0.5f;
            const float y = ypix - 0.5f;
            const float fx0 = floorf(x), fy0 = floorf(y);
            const float wx1 = x - fx0,   wy1 = y - fy0;
            const float wx0 = 1.f - wx1, wy0 = 1.f - wy1;
            const int ix0 = (int)fx0, iy0 = (int)fy0;
            const bool vx0 = (ix0 >= 0), vy0 = (iy0 >= 0);
            const int cx0 = max(ix0, 0), cy0 = max(iy0, 0);
            const int cx1 = ix0 + 1,     cy1 = iy0 + 1;   // in-bounds given valid

            const int base = s * HFD;
            int4 o;
            o.x = ((base + cy0) * WFD + cx0) * (NC/2);
            o.y = ((base + cy0) * WFD + cx1) * (NC/2);
            o.z = ((base + cy1) * WFD + cx0) * (NC/2);
            o.w = ((base + cy1) * WFD + cx1) * (NC/2);
            ent_o[vox][s] = o;

            const float w00 = (vx0 && vy0) ? wx0 * wy0 : 0.f;
            const float w10 = vy0 ? wx1 * wy0 : 0.f;
            const float w01 = vx0 ? wx0 * wy1 : 0.f;
            const float w11 = wx1 * wy1;
            uint4 w;
            __half2 h;
            h = __float2half2_rn(w00); w.x = *reinterpret_cast<unsigned*>(&h);
            h = __float2half2_rn(w10); w.y = *reinterpret_cast<unsigned*>(&h);
            h = __float2half2_rn(w01); w.z = *reinterpret_cast<unsigned*>(&h);
            h = __float2half2_rn(w11); w.w = *reinterpret_cast<unsigned*>(&h);
            ent_w[vox][s] = w;

            atomicOr(&vmask[vox], 1 << s);
        }
    }
    __syncthreads();

    // ---- Sampling phase: warp processes its 4 voxels in ONE pass ----
    const int warp = tid >> 5;
    const int lane = tid & 31;
    const int q    = lane >> 3;      // voxel within warp's group of 4
    const int e    = lane & 7;       // channel oct: channels [8e, 8e+8)
    const int e4   = e * 4;          // in half2 units
    const __half2* __restrict__ ft2 = reinterpret_cast<const __half2*>(g_featT);
    const __half2 h2zero = __float2half2_rn(0.f);
    const float inv1eps = 0.99999899999f;   // 1/(1+1e-6)

    {
        const int v = warp * 4 + q;              // per-lane voxel
        const int m = vmask[v];                  // LDS, 4 addrs per warp
        float* accrow = &acc[v * 68 + e * 8];

        if (__all_sync(0xffffffffu, (m & (m - 1)) == 0)) {
            // all 4 voxels have <= 1 camera (common case)
            float4 lo = make_float4(0.f, 0.f, 0.f, 0.f);
            float4 hi = make_float4(0.f, 0.f, 0.f, 0.f);
            if (m) {
                const int s = __ffs(m) - 1;      // uniform per octet
                __half2 r[4];
                sample_cam4(ft2, ent_o[v][s], ent_w[v][s], e4, r);
                const float2 f0 = __half22float2(r[0]);
                const float2 f1 = __half22float2(r[1]);
                const float2 f2 = __half22float2(r[2]);
                const float2 f3 = __half22float2(r[3]);
                lo = make_float4(f0.x * inv1eps, f0.y * inv1eps,
                                 f1.x * inv1eps, f1.y * inv1eps);
                hi = make_float4(f2.x * inv1eps, f2.y * inv1eps,
                                 f3.x * inv1eps, f3.y * inv1eps);
            }
            *reinterpret_cast<float4*>(accrow)     = lo;
            *reinterpret_cast<float4*>(accrow + 4) = hi;
        } else {
            float sum[8];
            __half2 cnt[4];
#pragma unroll
            for (int j = 0; j < 8; j++) sum[j] = 0.f;
#pragma unroll
            for (int j = 0; j < 4; j++) cnt[j] = h2zero;
            int mm = m;
            while (__any_sync(0xffffffffu, mm != 0)) {
                if (mm) {
                    const int s = __ffs(mm) - 1;     // ascending -> deterministic
                    mm &= mm - 1;
                    __half2 r[4];
                    sample_cam4(ft2, ent_o[v][s], ent_w[v][s], e4, r);
#pragma unroll
                    for (int j = 0; j < 4; j++) {
                        const float2 f = __half22float2(r[j]);
                        sum[2*j]   += f.x;
                        sum[2*j+1] += f.y;
                        cnt[j] = __hadd2(cnt[j], __hne2(r[j], h2zero));
                    }
                }
            }
            float4 lo, hi;
            float* lop = &lo.x; float* hip = &hi.x;
#pragma unroll
            for (int j = 0; j < 4; j++) {
                const float2 c = __half22float2(cnt[j]);
                float r0 = sum[2*j]   * __fdividef(1.0f, c.x + 1e-6f);
                float r1 = sum[2*j+1] * __fdividef(1.0f, c.y + 1e-6f);
                if (j < 2) { lop[2*j] = r0; lop[2*j+1] = r1; }
                else       { hip[2*(j-2)] = r0; hip[2*(j-2)+1] = r1; }
            }
            *reinterpret_cast<float4*>(accrow)     = lo;
            *reinterpret_cast<float4*>(accrow + 4) = hi;
        }
    }
    __syncthreads();

    // ---- Write phase: STG.128, warp writes 128B-contiguous per channel ----
#pragma unroll
    for (int t = 0; t < 2; t++) {
        const int v4 = tid & 7;
        const int c  = (tid >> 3) + t * 32;
        float4 v;
        v.x = acc[(4*v4 + 0) * 68 + c];
        v.y = acc[(4*v4 + 1) * 68 + c];
        v.z = acc[(4*v4 + 2) * 68 + c];
        v.w = acc[(4*v4 + 3) * 68 + c];
        *reinterpret_cast<float4*>(out + c * NVOX + ovBase + 4*v4) = v;
    }
}

// ---------------------------------------------------------------------------
extern "C" void kernel_launch(void* const* d_in, const int* in_sizes, int n_in,
                              void* d_out, int out_size) {
    int fi = 0;
    for (int i = 0; i < n_in; i++)
        if (in_sizes[i] == NS * NC * HFD * WFD) { fi = i; break; }
    int mi0 = -1, mi1 = -1;
    for (int i = 0; i < n_in; i++) {
        if (i == fi) continue;
        if (mi0 < 0) mi0 = i; else if (mi1 < 0) mi1 = i;
    }
    const float* features = (const float*)d_in[fi];
    const float* pix      = (const float*)d_in[mi0];   // pix_T_cams
    const float* c0x      = (const float*)d_in[mi1];   // cam0_T_camXs

    dim3 tb(32, 8);
    dim3 tg(HW / 32, 1, NS);
    transpose_feat<<<tg, tb>>>(features, pix, c0x);

    sample_kernel<<<NVOX / 32, 256>>>((float*)d_out);
}

// round 11
// speedup vs baseline: 1.4361x; 1.1175x over previous
#include <cuda_runtime.h>
#include <cuda_fp16.h>

#define NS    6
#define NC    64
#define HFD   44
#define WFD   80
#define HW    (HFD*WFD)       // 3520
#define ZD    16
#define YD    100
#define XD    100
#define NVOX  (XD*YD*ZD)      // 160000

// Scratch (no cudaMalloc allowed)
__device__ __align__(16) __half g_featT[NS*HW*NC];  // [s][h][w][c], fp16
__device__ float  g_M[NS][12];        // rows 0..2 of featpix_T_cams @ inv(cam0_T_camXs)
__device__ float  g_Zrow[NS][4];      // row 2 of inv(cam0_T_camXs)

// ---------------------------------------------------------------------------
// Matrix prep (device helper, run by spare threads of transpose block 0)
// ---------------------------------------------------------------------------
__device__ void prep_one(int s, const float* __restrict__ pix,
                         const float* __restrict__ c0x) {
    const float* K = pix + s * 16;
    const float* T = c0x + s * 16;

    float inv[4][4];
#pragma unroll
    for (int i = 0; i < 4; i++)
#pragma unroll
        for (int j = 0; j < 4; j++) inv[i][j] = 0.f;
#pragma unroll
    for (int i = 0; i < 3; i++)
#pragma unroll
        for (int j = 0; j < 3; j++) inv[i][j] = T[j*4 + i];   // R^T
#pragma unroll
    for (int i = 0; i < 3; i++) {
        float v = 0.f;
#pragma unroll
        for (int j = 0; j < 3; j++) v += T[j*4 + i] * T[j*4 + 3];
        inv[i][3] = -v;
    }
    inv[3][3] = 1.f;

    const float sx = (float)WFD / 640.0f;   // 0.125
    const float sy = (float)HFD / 352.0f;   // 0.125
    float FP[4][4];
#pragma unroll
    for (int j = 0; j < 4; j++) {
        FP[0][j] = sx * K[j];
        FP[1][j] = sy * K[4 + j];
        FP[2][j] = K[8 + j];
        FP[3][j] = K[12 + j];
    }

#pragma unroll
    for (int i = 0; i < 3; i++)
#pragma unroll
        for (int j = 0; j < 4; j++) {
            float v = 0.f;
#pragma unroll
            for (int k = 0; k < 4; k++) v += FP[i][k] * inv[k][j];
            g_M[s][i*4 + j] = v;
        }
#pragma unroll
    for (int j = 0; j < 4; j++) g_Zrow[s][j] = inv[2][j];
}

// ---------------------------------------------------------------------------
// Kernel 1: transpose [S,C,H,W] fp32 -> [S,H,W,C] fp16 (half2 writes),
//           + fused matrix prep.  Tile: 64 channels x 32 pixels.
// ---------------------------------------------------------------------------
__global__ void transpose_feat(const float* __restrict__ in,
                               const float* __restrict__ pix,
                               const float* __restrict__ c0x) {
    __shared__ float tile[64][33];
    const int s     = blockIdx.z;
    const int pBase = blockIdx.x * 32;
    const int tx = threadIdx.x, ty = threadIdx.y;  // (32, 8)

    if (blockIdx.x == 0 && blockIdx.z == 0 && ty == 7 && tx < NS)
        prep_one(tx, pix, c0x);

    const float* ip = in + s * NC * HW;
#pragma unroll
    for (int k = 0; k < 8; k++) {
        int c = ty + k*8;
        tile[c][tx] = ip[c * HW + pBase + tx];   // coalesced in p
    }
    __syncthreads();
    __half2* op = reinterpret_cast<__half2*>(g_featT + s * HW * NC);
#pragma unroll
    for (int k = 0; k < 4; k++) {
        int p = pBase + ty + k*8;
        int pp = ty + k*8;
        __half2 h = __floats2half2_rn(tile[2*tx][pp], tile[2*tx + 1][pp]);
        op[p * (NC/2) + tx] = h;                 // 128B coalesced per warp
    }
}

// ---------------------------------------------------------------------------
// Kernel 2: project + bilinear sample + camera reduction
// Block: 256 threads, 32 voxels.
// Projection: warp = camera (6 warps), lane = voxel; validity via ballot.
// Sampling:   warp = 4 voxels, lane>>3 = voxel, lane&7 = channel octet.
// acc staging uses a per-voxel rotated layout -> all smem phases conflict-free.
// ---------------------------------------------------------------------------
__device__ __forceinline__ void sample_cam4(const __half2* __restrict__ ft2,
                                            const int4 o, const uint4 wp,
                                            int e4, __half2 r[4]) {
    const uint4 a = *reinterpret_cast<const uint4*>(ft2 + o.x + e4);
    const uint4 b = *reinterpret_cast<const uint4*>(ft2 + o.y + e4);
    const uint4 c = *reinterpret_cast<const uint4*>(ft2 + o.z + e4);
    const uint4 d = *reinterpret_cast<const uint4*>(ft2 + o.w + e4);
    const __half2 w00 = *reinterpret_cast<const __half2*>(&wp.x);
    const __half2 w10 = *reinterpret_cast<const __half2*>(&wp.y);
    const __half2 w01 = *reinterpret_cast<const __half2*>(&wp.z);
    const __half2 w11 = *reinterpret_cast<const __half2*>(&wp.w);
    const unsigned* ap = &a.x; const unsigned* bp = &b.x;
    const unsigned* cp = &c.x; const unsigned* dp = &d.x;
#pragma unroll
    for (int j = 0; j < 4; j++) {
        __half2 t = __hmul2(w00, *reinterpret_cast<const __half2*>(&ap[j]));
        t = __hfma2(w10, *reinterpret_cast<const __half2*>(&bp[j]), t);
        t = __hfma2(w01, *reinterpret_cast<const __half2*>(&cp[j]), t);
        t = __hfma2(w11, *reinterpret_cast<const __half2*>(&dp[j]), t);
        r[j] = t;
    }
}

__global__ void __launch_bounds__(256) sample_kernel(float* __restrict__ out) {
    __shared__ int4     ent_o[32][7];   // stride 7 -> conflict-free stores (3.5 KB)
    __shared__ uint4    ent_w[32][7];   // (3.5 KB)
    __shared__ unsigned bal_sm[8];      // per-camera voxel validity (padded to 32B)
    __shared__ __align__(16) float acc[32 * 64];   // rotated layout, 8 KB, 16B-aligned

    const int tid    = threadIdx.x;
    const int lane   = tid & 31;
    const int warp   = tid >> 5;
    const int ovBase = blockIdx.x * 32;

    // ---- Projection phase: warp = camera s (warps 0..5), lane = voxel ----
    if (warp < NS) {
        const int s   = warp;
        const int vox = lane;

        const int ov  = ovBase + vox;
        const int ix  = ov / 1600;
        const int rem = ov - ix * 1600;
        const int iy  = rem >> 4;
        const int iz  = rem & 15;

        const float px = fmaf(0.8f, (float)ix + 0.5f, -40.0f);
        const float py = fmaf(0.8f, (float)iy + 0.5f, -40.0f);
        const float pz = fmaf(0.4f, (float)iz + 0.5f, -1.0f);

        const float* M  = g_M[s];    // warp-uniform
        const float* Zr = g_Zrow[s];
        const float xp = fmaf(M[0], px, fmaf(M[1], py, fmaf(M[2],  pz, M[3])));
        const float yp = fmaf(M[4], px, fmaf(M[5], py, fmaf(M[6],  pz, M[7])));
        const float zp = fmaf(M[8], px, fmaf(M[9], py, fmaf(M[10], pz, M[11])));
        const float zc = fmaf(Zr[0], px, fmaf(Zr[1], py, fmaf(Zr[2], pz, Zr[3])));

        const float rden = __fdividef(1.0f, fmaxf(zp, 1e-6f));
        const float xpix = xp * rden;
        const float ypix = yp * rden;

        const bool valid = (xpix > -0.5f) && (xpix < (float)WFD - 0.5f) &&
                           (ypix > -0.5f) && (ypix < (float)HFD - 0.5f) &&
                           (zc > 0.0f);
        const unsigned bal = __ballot_sync(0xffffffffu, valid);
        if (lane == 0) bal_sm[s] = bal;

        if (valid) {
            const float x = xpix - 0.5f;
            const float y = ypix - 0.5f;
            const float fx0 = floorf(x), fy0 = floorf(y);
            const float wx1 = x - fx0,   wy1 = y - fy0;
            const float wx0 = 1.f - wx1, wy0 = 1.f - wy1;
            const int ix0 = (int)fx0, iy0 = (int)fy0;
            const bool vx0 = (ix0 >= 0), vy0 = (iy0 >= 0);
            const int cx0 = max(ix0, 0), cy0 = max(iy0, 0);
            const int cx1 = ix0 + 1,     cy1 = iy0 + 1;   // in-bounds given valid

            const int base = s * HFD;
            int4 o;
            o.x = ((base + cy0) * WFD + cx0) * (NC/2);
            o.y = ((base + cy0) * WFD + cx1) * (NC/2);
            o.z = ((base + cy1) * WFD + cx0) * (NC/2);
            o.w = ((base + cy1) * WFD + cx1) * (NC/2);
            ent_o[vox][s] = o;

            const float w00 = (vx0 && vy0) ? wx0 * wy0 : 0.f;
            const float w10 = vy0 ? wx1 * wy0 : 0.f;
            const float w01 = vx0 ? wx0 * wy1 : 0.f;
            const float w11 = wx1 * wy1;
            uint4 w;
            __half2 h;
            h = __float2half2_rn(w00); w.x = *reinterpret_cast<unsigned*>(&h);
            h = __float2half2_rn(w10); w.y = *reinterpret_cast<unsigned*>(&h);
            h = __float2half2_rn(w01); w.z = *reinterpret_cast<unsigned*>(&h);
            h = __float2half2_rn(w11); w.w = *reinterpret_cast<unsigned*>(&h);
            ent_w[vox][s] = w;
        }
    }
    __syncthreads();

    // ---- Sampling phase: warp processes its 4 voxels in one pass ----
    const int q  = lane >> 3;        // voxel within warp's group of 4
    const int e  = lane & 7;         // channel octet: channels [8e, 8e+8)
    const int e4 = e * 4;            // in half2 units
    const int v  = warp * 4 + q;     // per-lane voxel
    const __half2* __restrict__ ft2 = reinterpret_cast<const __half2*>(g_featT);
    const __half2 h2zero = __float2half2_rn(0.f);
    const float inv1eps = 0.99999899999f;   // 1/(1+1e-6)

    int m = 0;
#pragma unroll
    for (int s2 = 0; s2 < NS; s2++)
        m |= (int)((bal_sm[s2] >> v) & 1u) << s2;

    // rotated columns: channel c of voxel v lives at (c + 4*(v>>2) + 4*(v&3)) & 63
    const int colA = (8*e + 4*warp + 4*q) & 63;
    const int colB = (colA + 4) & 63;
    float* accA = &acc[v * 64 + colA];
    float* accB = &acc[v * 64 + colB];

    if (__all_sync(0xffffffffu, (m & (m - 1)) == 0)) {
        // all 4 voxels have <= 1 camera (common case)
        float4 lo = make_float4(0.f, 0.f, 0.f, 0.f);
        float4 hi = make_float4(0.f, 0.f, 0.f, 0.f);
        if (m) {
            const int s = __ffs(m) - 1;
            __half2 r[4];
            sample_cam4(ft2, ent_o[v][s], ent_w[v][s], e4, r);
            const float2 f0 = __half22float2(r[0]);
            const float2 f1 = __half22float2(r[1]);
            const float2 f2 = __half22float2(r[2]);
            const float2 f3 = __half22float2(r[3]);
            lo = make_float4(f0.x * inv1eps, f0.y * inv1eps,
                             f1.x * inv1eps, f1.y * inv1eps);
            hi = make_float4(f2.x * inv1eps, f2.y * inv1eps,
                             f3.x * inv1eps, f3.y * inv1eps);
        }
        *reinterpret_cast<float4*>(accA) = lo;
        *reinterpret_cast<float4*>(accB) = hi;
    } else {
        float sum[8];
        __half2 cnt[4];
#pragma unroll
        for (int j = 0; j < 8; j++) sum[j] = 0.f;
#pragma unroll
        for (int j = 0; j < 4; j++) cnt[j] = h2zero;
        int mm = m;
        while (__any_sync(0xffffffffu, mm != 0)) {
            if (mm) {
                const int s = __ffs(mm) - 1;     // ascending -> deterministic
                mm &= mm - 1;
                __half2 r[4];
                sample_cam4(ft2, ent_o[v][s], ent_w[v][s], e4, r);
#pragma unroll
                for (int j = 0; j < 4; j++) {
                    const float2 f = __half22float2(r[j]);
                    sum[2*j]   += f.x;
                    sum[2*j+1] += f.y;
                    cnt[j] = __hadd2(cnt[j], __hne2(r[j], h2zero));
                }
            }
        }
        float4 lo, hi;
        float* lop = &lo.x; float* hip = &hi.x;
#pragma unroll
        for (int j = 0; j < 4; j++) {
            const float2 c = __half22float2(cnt[j]);
            float r0 = sum[2*j]   * __fdividef(1.0f, c.x + 1e-6f);
            float r1 = sum[2*j+1] * __fdividef(1.0f, c.y + 1e-6f);
            if (j < 2) { lop[2*j] = r0; lop[2*j+1] = r1; }
            else       { hip[2*(j-2)] = r0; hip[2*(j-2)+1] = r1; }
        }
        *reinterpret_cast<float4*>(accA) = lo;
        *reinterpret_cast<float4*>(accB) = hi;
    }
    __syncthreads();

    // ---- Write phase: conflict-free rotated reads + STG.128 ----
#pragma unroll
    for (int t = 0; t < 2; t++) {
        const int v4 = tid & 7;
        const int c  = (tid >> 3) + t * 32;
        float4 r;
        r.x = acc[(4*v4 + 0) * 64 + ((c + 4*v4 +  0) & 63)];
        r.y = acc[(4*v4 + 1) * 64 + ((c + 4*v4 +  4) & 63)];
        r.z = acc[(4*v4 + 2) * 64 + ((c + 4*v4 +  8) & 63)];
        r.w = acc[(4*v4 + 3) * 64 + ((c + 4*v4 + 12) & 63)];
        *reinterpret_cast<float4*>(out + c * NVOX + ovBase + 4*v4) = r;
    }
}

// ---------------------------------------------------------------------------
extern "C" void kernel_launch(void* const* d_in, const int* in_sizes, int n_in,
                              void* d_out, int out_size) {
    int fi = 0;
    for (int i = 0; i < n_in; i++)
        if (in_sizes[i] == NS * NC * HFD * WFD) { fi = i; break; }
    int mi0 = -1, mi1 = -1;
    for (int i = 0; i < n_in; i++) {
        if (i == fi) continue;
        if (mi0 < 0) mi0 = i; else if (mi1 < 0) mi1 = i;
    }
    const float* features = (const float*)d_in[fi];
    const float* pix      = (const float*)d_in[mi0];   // pix_T_cams
    const float* c0x      = (const float*)d_in[mi1];   // cam0_T_camXs

    dim3 tb(32, 8);
    dim3 tg(HW / 32, 1, NS);
    transpose_feat<<<tg, tb>>>(features, pix, c0x);

    sample_kernel<<<NVOX / 32, 256>>>((float*)d_out);
}